// round 13
// baseline (speedup 1.0000x reference)
#include <cuda_runtime.h>
#include <cuda.h>
#include <cuda_fp16.h>
#include <stdint.h>
#include <math.h>

// ---------------- problem constants ----------------
#define BATCH 8
#define SEQ   4096
#define CDIM  512
#define NHEAD 16
#define HDIM  32
#define MROWS (BATCH*SEQ)          // 32768
#define EPS_LN 1e-6f
#define EPS_ATT 1e-6f

typedef unsigned short h16;        // raw fp16 storage (avoid __half lvalues)

__device__ __forceinline__ h16 f2h(float v) { return __half_as_ushort(__float2half_rn(v)); }
__device__ __forceinline__ float h2f(h16 s) { return __half2float(__ushort_as_half(s)); }

// ---------------- scratch (static device globals) ----------------
__device__ h16 g_Qh[MROWS*CDIM];     // elu(q)+1, fp16
__device__ h16 g_Kh[MROWS*CDIM];     // elu(k)+1, fp16
__device__ h16 g_Vh[MROWS*CDIM];     // v (UNscaled), fp16
__device__ h16 g_x2h[MROWS*CDIM];    // x + msg@Wm, fp16
__device__ h16 g_Ah[MROWS*CDIM];     // LN output (fp16)
__device__ h16 g_Mh[MROWS*CDIM];     // msg / gelu output (fp16)
__device__ h16 g_Whi[6*CDIM*CDIM];   // [N][K] transposed, fp16
__device__ float g_KV  [BATCH*NHEAD*HDIM*HDIM];
__device__ float g_Ksum[BATCH*NHEAD*HDIM];

// ---------------- PTX helpers ----------------
__device__ __forceinline__ uint32_t smem_u32(const void* p) {
    uint32_t a;
    asm("{ .reg .u64 t; cvta.to.shared.u64 t, %1; cvt.u32.u64 %0, t; }" : "=r"(a) : "l"(p));
    return a;
}
__device__ __forceinline__ void cp16(uint32_t dst, const void* src) {
    asm volatile("cp.async.cg.shared.global [%0], [%1], 16;" :: "r"(dst), "l"(src));
}
__device__ __forceinline__ void cp_commit() {
    asm volatile("cp.async.commit_group;");
}
__device__ __forceinline__ void cp_wait1() {
    asm volatile("cp.async.wait_group 1;");
}
__device__ __forceinline__ void ldsm4(uint32_t* r, uint32_t addr) {
    asm volatile("ldmatrix.sync.aligned.m8n8.x4.shared.b16 {%0,%1,%2,%3}, [%4];"
        : "=r"(r[0]), "=r"(r[1]), "=r"(r[2]), "=r"(r[3]) : "r"(addr));
}
__device__ __forceinline__ void mma16816(float* c, const uint32_t* a, const uint32_t* b) {
    asm volatile("mma.sync.aligned.m16n8k16.row.col.f32.f16.f16.f32 "
        "{%0,%1,%2,%3}, {%4,%5,%6,%7}, {%8,%9}, {%0,%1,%2,%3};"
        : "+f"(c[0]), "+f"(c[1]), "+f"(c[2]), "+f"(c[3])
        : "r"(a[0]), "r"(a[1]), "r"(a[2]), "r"(a[3]), "r"(b[0]), "r"(b[1]));
}

// ---------------- HMMA GEMM: plain fp16, fp32 accum --------------------------
// D = A @ B^T   (A [M][K] fp16, B [N][K] fp16)
// CTA tile 128x128, BK=64 halves, 8 chunks, 2-stage double-buffered cp.async.
// epi: 2 = +res(f32) -> h16 ; 3 = gelu(acc+bias) -> h16 ; 4 = acc+bias+res(h16) -> f32
//      5 = merged QKV -> h16: w=bx>>2; Q,K get elu+1, V plain
#define HBM 128
#define HBN 128
#define HBK 64
#define LDP 72                      // padded row length in halves (144B)
#define SUBT (HBM*LDP*2)            // one 128x64 subtile = 18432 B
#define STAGE_B (2*SUBT)            // A + B = 36864 B
#define NCHUNK 8

__device__ __forceinline__ void load_chunk_dev(
    int c, int s, uint32_t sbase, int row0, int n0, int ldrow, int q0,
    const h16* A, const h16* B)
{
    const int k0 = c << 6;
    const uint32_t sA = sbase + s * STAGE_B;
    const uint32_t sB = sA + SUBT;
    const size_t ga = (size_t)(row0 + ldrow) * CDIM + k0;
    const size_t gb = (size_t)(n0 + ldrow) * CDIM + k0;
    #pragma unroll
    for (int i = 0; i < 4; i++) {
        const int q = q0 + i;
        cp16(sA + (ldrow * LDP + q * 8) * 2, A + ga + q * 8);
        cp16(sB + (ldrow * LDP + q * 8) * 2, B + gb + q * 8);
    }
    cp_commit();
}

__global__ __launch_bounds__(256, 2) void gemm_hmma(
          const h16* __restrict__ A, const h16* __restrict__ Bbase,
          float* __restrict__ out,
          h16* __restrict__ out_h,
          const float* __restrict__ bias, const float* __restrict__ res,
          const h16* __restrict__ resh,
          int epi,
          h16* __restrict__ outK, h16* __restrict__ outV)
{
    extern __shared__ char smem[];
    const uint32_t sbase = smem_u32(smem);
    const int tid = threadIdx.x;
    const int wid = tid >> 5, lane = tid & 31;
    const int warp_m = wid >> 2;
    const int warp_n = wid & 3;
    const int row0 = blockIdx.y * HBM;

    int n0, e;                 // e: 0=elu+1->h16, 1=plain->h16, 2=+res->h16, 3=gelu->h16, 4=+bias+res->f32
    const h16* B;
    h16* oh;
    if (epi == 5) {
        const int w = blockIdx.x >> 2;
        n0 = (blockIdx.x & 3) * HBN;
        B = Bbase + (size_t)w * CDIM * CDIM;
        oh = (w == 0) ? out_h : ((w == 1) ? outK : outV);
        e = (w == 2) ? 1 : 0;
    } else {
        n0 = blockIdx.x * HBN;
        B = Bbase;
        oh = out_h;
        e = epi;
    }

    const int ldrow = tid >> 1;          // 0..127
    const int q0 = (tid & 1) * 4;        // quad base (4 quads per thread per tensor)

    float acc[4][4][4];
    #pragma unroll
    for (int i = 0; i < 4; i++)
        #pragma unroll
        for (int j = 0; j < 4; j++)
            #pragma unroll
            for (int ee = 0; ee < 4; ee++) acc[i][j][ee] = 0.0f;

    // prologue: chunks 0 and 1
    load_chunk_dev(0, 0, sbase, row0, n0, ldrow, q0, A, B);
    load_chunk_dev(1, 1, sbase, row0, n0, ldrow, q0, A, B);

    const int b_row_lo = (lane >> 4) & 1;
    const int b_kh     = (lane >> 3) & 1;
    const int b_r7     = lane & 7;

    for (int c = 0; c < NCHUNK; c++) {
        const int s = c & 1;
        cp_wait1();                      // chunk c resident (c+1 may be in flight)
        __syncthreads();

        const uint32_t sA = sbase + s * STAGE_B;
        const uint32_t sB = sA + SUBT;
        #pragma unroll
        for (int kk = 0; kk < HBK; kk += 16) {
            uint32_t b[4][2];
            #pragma unroll
            for (int fnp = 0; fnp < 2; fnp++) {
                uint32_t r4[4];
                const int r = warp_n * 32 + (2 * fnp + b_row_lo) * 8 + b_r7;
                ldsm4(r4, sB + (r * LDP + kk + 8 * b_kh) * 2);
                b[2 * fnp + 0][0] = r4[0]; b[2 * fnp + 0][1] = r4[1];
                b[2 * fnp + 1][0] = r4[2]; b[2 * fnp + 1][1] = r4[3];
            }
            uint32_t a[4][4];
            #pragma unroll
            for (int fm = 0; fm < 4; fm++) {
                const int r = warp_m * 64 + fm * 16 + (lane & 15);
                ldsm4(a[fm], sA + (r * LDP + kk + 8 * (lane >> 4)) * 2);
            }
            #pragma unroll
            for (int fm = 0; fm < 4; fm++)
                #pragma unroll
                for (int fn = 0; fn < 4; fn++)
                    mma16816(acc[fm][fn], a[fm], b[fn]);
        }
        __syncthreads();
        if (c + 2 < NCHUNK)
            load_chunk_dev(c + 2, s, sbase, row0, n0, ldrow, q0, A, B);
    }

    // ---------------- epilogue ----------------
    const int g = lane >> 2;
    const int t2 = (lane & 3) * 2;
    #pragma unroll
    for (int fm = 0; fm < 4; fm++) {
        #pragma unroll
        for (int fn = 0; fn < 4; fn++) {
            const int ra = row0 + warp_m * 64 + fm * 16 + g;
            const int rb = ra + 8;
            const int col = n0 + warp_n * 32 + fn * 8 + t2;
            float v0 = acc[fm][fn][0], v1 = acc[fm][fn][1];
            float v2 = acc[fm][fn][2], v3 = acc[fm][fn][3];
            const size_t ia = (size_t)ra * CDIM + col;
            const size_t ib = (size_t)rb * CDIM + col;

            if (e == 4) {
                const float b0 = bias[col], b1 = bias[col + 1];
                v0 += b0 + h2f(resh[ia]); v1 += b1 + h2f(resh[ia + 1]);
                v2 += b0 + h2f(resh[ib]); v3 += b1 + h2f(resh[ib + 1]);
                float2 pa; pa.x = v0; pa.y = v1;
                float2 pb; pb.x = v2; pb.y = v3;
                *(float2*)(out + ia) = pa;
                *(float2*)(out + ib) = pb;
            } else {
                if (e == 0) {
                    v0 = (v0 > 0.0f) ? (v0 + 1.0f) : expf(v0);
                    v1 = (v1 > 0.0f) ? (v1 + 1.0f) : expf(v1);
                    v2 = (v2 > 0.0f) ? (v2 + 1.0f) : expf(v2);
                    v3 = (v3 > 0.0f) ? (v3 + 1.0f) : expf(v3);
                } else if (e == 2) {
                    v0 += res[ia]; v1 += res[ia + 1];
                    v2 += res[ib]; v3 += res[ib + 1];
                } else if (e == 3) {
                    const float b0 = bias[col], b1 = bias[col + 1];
                    v0 += b0; v1 += b1; v2 += b0; v3 += b1;
                    v0 = 0.5f * v0 * (1.0f + erff(v0 * 0.70710678f));
                    v1 = 0.5f * v1 * (1.0f + erff(v1 * 0.70710678f));
                    v2 = 0.5f * v2 * (1.0f + erff(v2 * 0.70710678f));
                    v3 = 0.5f * v3 * (1.0f + erff(v3 * 0.70710678f));
                }
                h16 h0 = f2h(v0), h1 = f2h(v1), h2 = f2h(v2), h3 = f2h(v3);
                *(uint32_t*)(oh + ia) = (uint32_t)h0 | ((uint32_t)h1 << 16);
                *(uint32_t*)(oh + ib) = (uint32_t)h2 | ((uint32_t)h3 << 16);
            }
        }
    }
}

// ---------------- weight transpose -> fp16 (all 6 in one launch) --------------
__global__ void transpose6(const float* __restrict__ W0, const float* __restrict__ W1,
                           const float* __restrict__ W2, const float* __restrict__ W3,
                           const float* __restrict__ W4, const float* __restrict__ W5,
                           h16* __restrict__ Tbase) {
    __shared__ float t[32][33];
    const int z = blockIdx.z;
    const float* W = (z == 0) ? W0 : (z == 1) ? W1 : (z == 2) ? W2 : (z == 3) ? W3 : (z == 4) ? W4 : W5;
    h16* T = Tbase + (size_t)z * CDIM * CDIM;
    const int n = blockIdx.x * 32 + threadIdx.x;
    #pragma unroll
    for (int r = 0; r < 4; ++r) {
        const int k = blockIdx.y * 32 + threadIdx.y + r * 8;
        t[threadIdx.y + r * 8][threadIdx.x] = W[(size_t)k * CDIM + n];
    }
    __syncthreads();
    #pragma unroll
    for (int r = 0; r < 4; ++r) {
        const int n_out = blockIdx.x * 32 + threadIdx.y + r * 8;
        const int k_out = blockIdx.y * 32 + threadIdx.x;
        T[(size_t)n_out * CDIM + k_out] = f2h(t[threadIdx.x][threadIdx.y + r * 8]);
    }
}

// ---------------- LayerNorm: warp-per-row, no block barriers ------------------
__global__ void ln_f32(const float* __restrict__ x,
                       const float* __restrict__ gam,
                       const float* __restrict__ bet,
                       h16* __restrict__ oh) {
    const int warp = threadIdx.x >> 5, lane = threadIdx.x & 31;
    const int row = blockIdx.x * 8 + warp;
    const float4* xr = (const float4*)(x + (size_t)row * CDIM);
    float4 v[4];
    float s = 0.0f, sq = 0.0f;
    #pragma unroll
    for (int j = 0; j < 4; j++) {
        v[j] = xr[j * 32 + lane];
        s  += v[j].x + v[j].y + v[j].z + v[j].w;
        sq += v[j].x * v[j].x + v[j].y * v[j].y + v[j].z * v[j].z + v[j].w * v[j].w;
    }
    #pragma unroll
    for (int o = 16; o; o >>= 1) {
        s  += __shfl_xor_sync(0xffffffffu, s,  o);
        sq += __shfl_xor_sync(0xffffffffu, sq, o);
    }
    const float mu = s * (1.0f / CDIM);
    const float rstd = rsqrtf(sq * (1.0f / CDIM) - mu * mu + EPS_LN);
    uint32_t* orow = (uint32_t*)(oh + (size_t)row * CDIM);
    const float4* gr = (const float4*)gam;
    const float4* br = (const float4*)bet;
    #pragma unroll
    for (int j = 0; j < 4; j++) {
        const float4 g4 = gr[j * 32 + lane];
        const float4 b4 = br[j * 32 + lane];
        const float o0 = (v[j].x - mu) * rstd * g4.x + b4.x;
        const float o1 = (v[j].y - mu) * rstd * g4.y + b4.y;
        const float o2 = (v[j].z - mu) * rstd * g4.z + b4.z;
        const float o3 = (v[j].w - mu) * rstd * g4.w + b4.w;
        orow[(j * 32 + lane) * 2 + 0] = (uint32_t)f2h(o0) | ((uint32_t)f2h(o1) << 16);
        orow[(j * 32 + lane) * 2 + 1] = (uint32_t)f2h(o2) | ((uint32_t)f2h(o3) << 16);
    }
}

__global__ void ln_f16(const h16* __restrict__ xh,
                       const float* __restrict__ gam,
                       const float* __restrict__ bet,
                       h16* __restrict__ oh) {
    const int warp = threadIdx.x >> 5, lane = threadIdx.x & 31;
    const int row = blockIdx.x * 8 + warp;
    const uint2* xr = (const uint2*)(xh + (size_t)row * CDIM);
    float vx[4][4];
    float s = 0.0f, sq = 0.0f;
    #pragma unroll
    for (int j = 0; j < 4; j++) {
        const uint2 u = xr[j * 32 + lane];
        vx[j][0] = h2f((h16)(u.x & 0xffff));
        vx[j][1] = h2f((h16)(u.x >> 16));
        vx[j][2] = h2f((h16)(u.y & 0xffff));
        vx[j][3] = h2f((h16)(u.y >> 16));
        #pragma unroll
        for (int e = 0; e < 4; e++) { s += vx[j][e]; sq += vx[j][e] * vx[j][e]; }
    }
    #pragma unroll
    for (int o = 16; o; o >>= 1) {
        s  += __shfl_xor_sync(0xffffffffu, s,  o);
        sq += __shfl_xor_sync(0xffffffffu, sq, o);
    }
    const float mu = s * (1.0f / CDIM);
    const float rstd = rsqrtf(sq * (1.0f / CDIM) - mu * mu + EPS_LN);
    uint32_t* orow = (uint32_t*)(oh + (size_t)row * CDIM);
    const float4* gr = (const float4*)gam;
    const float4* br = (const float4*)bet;
    #pragma unroll
    for (int j = 0; j < 4; j++) {
        const float4 g4 = gr[j * 32 + lane];
        const float4 b4 = br[j * 32 + lane];
        const float o0 = (vx[j][0] - mu) * rstd * g4.x + b4.x;
        const float o1 = (vx[j][1] - mu) * rstd * g4.y + b4.y;
        const float o2 = (vx[j][2] - mu) * rstd * g4.z + b4.z;
        const float o3 = (vx[j][3] - mu) * rstd * g4.w + b4.w;
        orow[(j * 32 + lane) * 2 + 0] = (uint32_t)f2h(o0) | ((uint32_t)f2h(o1) << 16);
        orow[(j * 32 + lane) * 2 + 1] = (uint32_t)f2h(o2) | ((uint32_t)f2h(o3) << 16);
    }
}

// ---------------- zero KV/Ksum ----------------
__global__ void zero_kv_kernel() {
    int i = blockIdx.x * blockDim.x + threadIdx.x;
    if (i < BATCH * NHEAD * HDIM * HDIM) g_KV[i] = 0.0f;
    if (i < BATCH * NHEAD * HDIM)        g_Ksum[i] = 0.0f;
}

// ---------------- KV = sum_s K[s] (outer) v[s]; Ksum = sum_s K[s] -------------
__global__ void kv_kernel() {
    const int bh = blockIdx.x;
    const int b = bh >> 4, h = bh & 15;
    const int tid = threadIdx.x;
    const int d = tid >> 3;
    const int vb = (tid & 7) << 2;
    __shared__ float sK[16][32];
    __shared__ float sV[16][32];

    const int lrow  = tid >> 4;      // 0..15
    const int lpair = tid & 15;      // 0..15 (h16 pair)

    float a0 = 0, a1 = 0, a2 = 0, a3 = 0, ks = 0;
    const h16* Kbase = g_Kh + (size_t)b * SEQ * CDIM + h * HDIM;
    const h16* Vbase = g_Vh + (size_t)b * SEQ * CDIM + h * HDIM;
    const int s0 = blockIdx.y * (SEQ / 8);   // 512 tokens/block

    size_t so = (size_t)(s0 + lrow) * CDIM + lpair * 2;
    uint32_t kn = *(const uint32_t*)(Kbase + so);
    uint32_t vn = *(const uint32_t*)(Vbase + so);

    for (int ssi = 0; ssi < SEQ / 8; ssi += 16) {
        const uint32_t kc = kn, vc = vn;
        if (ssi + 16 < SEQ / 8) {
            const size_t s2 = (size_t)(s0 + ssi + 16 + lrow) * CDIM + lpair * 2;
            kn = *(const uint32_t*)(Kbase + s2);
            vn = *(const uint32_t*)(Vbase + s2);
        }
        sK[lrow][lpair * 2 + 0] = h2f((h16)(kc & 0xffff));
        sK[lrow][lpair * 2 + 1] = h2f((h16)(kc >> 16));
        sV[lrow][lpair * 2 + 0] = h2f((h16)(vc & 0xffff));
        sV[lrow][lpair * 2 + 1] = h2f((h16)(vc >> 16));
        __syncthreads();
        #pragma unroll
        for (int si = 0; si < 16; si++) {
            const float kd = sK[si][d];
            ks += kd;
            a0 = fmaf(kd, sV[si][vb + 0], a0);
            a1 = fmaf(kd, sV[si][vb + 1], a1);
            a2 = fmaf(kd, sV[si][vb + 2], a2);
            a3 = fmaf(kd, sV[si][vb + 3], a3);
        }
        __syncthreads();
    }
    float* kvp = g_KV + (size_t)bh * HDIM * HDIM + d * HDIM + vb;
    atomicAdd(kvp + 0, a0);
    atomicAdd(kvp + 1, a1);
    atomicAdd(kvp + 2, a2);
    atomicAdd(kvp + 3, a3);
    if ((tid & 7) == 0) atomicAdd(&g_Ksum[bh * HDIM + d], ks);
}

// ---------------- msg: per token-head 32x32 matvec -> fp16 --------------------
__global__ void msg_kernel() {
    const int bh = blockIdx.x;
    const int b = bh >> 4, h = bh & 15;
    const int tid = threadIdx.x;
    const int warp = tid >> 5, lane = tid & 31;
    __shared__ float sKV[HDIM * HDIM];
    __shared__ float sKs[HDIM];

    for (int i = tid; i < HDIM * HDIM; i += 256) sKV[i] = g_KV[(size_t)bh * HDIM * HDIM + i];
    if (tid < HDIM) sKs[tid] = g_Ksum[bh * HDIM + tid];
    __syncthreads();

    const int tokBase = blockIdx.y * 64 + warp * 8;
    for (int tt = 0; tt < 8; tt++) {
        const int s = tokBase + tt;
        const size_t off = ((size_t)b * SEQ + s) * CDIM + h * HDIM + lane;
        const float q = h2f(g_Qh[off]);
        float zp = q * sKs[lane];
        #pragma unroll
        for (int o = 16; o; o >>= 1) zp += __shfl_xor_sync(0xffffffffu, zp, o);
        float acc = 0.0f;
        #pragma unroll
        for (int dd = 0; dd < HDIM; dd++) {
            const float qd = __shfl_sync(0xffffffffu, q, dd);
            acc = fmaf(qd, sKV[dd * HDIM + lane], acc);
        }
        g_Mh[off] = f2h(acc / (zp + EPS_ATT));
    }
}

// ---------------- host side ----------------
extern "C" void kernel_launch(void* const* d_in, const int* in_sizes, int n_in,
                              void* d_out, int out_size) {
    const float* x     = (const float*)d_in[0];
    const float* Wq    = (const float*)d_in[1];
    const float* Wk    = (const float*)d_in[2];
    const float* Wv    = (const float*)d_in[3];
    const float* Wm    = (const float*)d_in[4];
    const float* W1    = (const float*)d_in[5];
    const float* b1    = (const float*)d_in[6];
    const float* W2    = (const float*)d_in[7];
    const float* b2    = (const float*)d_in[8];
    const float* g_att = (const float*)d_in[9];
    const float* b_att = (const float*)d_in[10];
    const float* g_ffn = (const float*)d_in[11];
    const float* b_ffn = (const float*)d_in[12];
    float* out = (float*)d_out;

    h16 *p_Qh, *p_Kh, *p_Vh, *p_x2h, *p_Ah, *p_Mh, *p_Whi;
    cudaGetSymbolAddress((void**)&p_Qh,  g_Qh);
    cudaGetSymbolAddress((void**)&p_Kh,  g_Kh);
    cudaGetSymbolAddress((void**)&p_Vh,  g_Vh);
    cudaGetSymbolAddress((void**)&p_x2h, g_x2h);
    cudaGetSymbolAddress((void**)&p_Ah,  g_Ah);
    cudaGetSymbolAddress((void**)&p_Mh,  g_Mh);
    cudaGetSymbolAddress((void**)&p_Whi, g_Whi);

    const int SMEM = 2 * STAGE_B;   // 73728
    cudaFuncSetAttribute(gemm_hmma, cudaFuncAttributeMaxDynamicSharedMemorySize, SMEM);

    const size_t WS = (size_t)CDIM * CDIM;
    dim3 tgrid(16, 16, 6);
    dim3 tblk(32, 8);
    dim3 ggrid(CDIM / HBN, MROWS / HBM);        // (4, 256)
    dim3 qkvgrid(3 * CDIM / HBN, MROWS / HBM);  // (12, 256)

    zero_kv_kernel<<<(BATCH * NHEAD * HDIM * HDIM + 255) / 256, 256>>>();
    transpose6<<<tgrid, tblk>>>(Wq, Wk, Wv, Wm, W1, W2, p_Whi);
    // h = LN(x) -> Ah
    ln_f32<<<MROWS / 8, 256>>>(x, g_att, b_att, p_Ah);
    // merged QKV (Q = elu+1, K = elu+1, V = plain) -> fp16
    gemm_hmma<<<qkvgrid, 256, SMEM>>>(p_Ah, p_Whi, nullptr, p_Qh, nullptr, nullptr, nullptr, 5, p_Kh, p_Vh);
    // KV / Ksum
    kv_kernel<<<dim3(BATCH * NHEAD, 8), 256>>>();
    // msg -> Mh
    msg_kernel<<<dim3(BATCH * NHEAD, SEQ / 64), 256>>>();
    // x2 = x + msg @ Wm  -> fp16
    gemm_hmma<<<ggrid, 256, SMEM>>>(p_Mh, p_Whi + 3*WS, nullptr, p_x2h, nullptr, x, nullptr, 2, nullptr, nullptr);
    // h2 = LN(x2) -> Ah
    ln_f16<<<MROWS / 8, 256>>>(p_x2h, g_ffn, b_ffn, p_Ah);
    // f1 = gelu(h2 @ W1 + b1) -> Mh
    gemm_hmma<<<ggrid, 256, SMEM>>>(p_Ah, p_Whi + 4*WS, nullptr, p_Mh, b1, nullptr, nullptr, 3, nullptr, nullptr);
    // out = x2 + f1 @ W2 + b2  (x2 read as fp16)
    gemm_hmma<<<ggrid, 256, SMEM>>>(p_Mh, p_Whi + 5*WS, out, nullptr, b2, nullptr, p_x2h, 4, nullptr, nullptr);
}

// round 14
// speedup vs baseline: 1.1525x; 1.1525x over previous
#include <cuda_runtime.h>
#include <cuda.h>
#include <cuda_fp16.h>
#include <stdint.h>
#include <math.h>

// ---------------- problem constants ----------------
#define BATCH 8
#define SEQ   4096
#define CDIM  512
#define NHEAD 16
#define HDIM  32
#define MROWS (BATCH*SEQ)          // 32768
#define EPS_LN 1e-6f
#define EPS_ATT 1e-6f

typedef unsigned short h16;        // raw fp16 storage (avoid __half lvalues)

__device__ __forceinline__ h16 f2h(float v) { return __half_as_ushort(__float2half_rn(v)); }
__device__ __forceinline__ float h2f(h16 s) { return __half2float(__ushort_as_half(s)); }

// ---------------- scratch (static device globals) ----------------
__device__ h16 g_Qh[MROWS*CDIM];     // elu(q)+1, fp16
__device__ h16 g_Kh[MROWS*CDIM];     // elu(k)+1, fp16
__device__ h16 g_Vh[MROWS*CDIM];     // v (UNscaled), fp16
__device__ h16 g_x2h[MROWS*CDIM];    // x + msg@Wm, fp16
__device__ h16 g_Ah[MROWS*CDIM];     // LN output (fp16)
__device__ h16 g_Mh[MROWS*CDIM];     // msg / gelu output (fp16)
__device__ h16 g_Whi[6*CDIM*CDIM];   // [N][K] transposed, fp16
__device__ float g_KV  [BATCH*NHEAD*HDIM*HDIM];
__device__ float g_Ksum[BATCH*NHEAD*HDIM];

// ---------------- PTX helpers ----------------
__device__ __forceinline__ uint32_t smem_u32(const void* p) {
    uint32_t a;
    asm("{ .reg .u64 t; cvta.to.shared.u64 t, %1; cvt.u32.u64 %0, t; }" : "=r"(a) : "l"(p));
    return a;
}
__device__ __forceinline__ void cp16(uint32_t dst, const void* src) {
    asm volatile("cp.async.cg.shared.global [%0], [%1], 16;" :: "r"(dst), "l"(src));
}
__device__ __forceinline__ void cp_commit() {
    asm volatile("cp.async.commit_group;");
}
__device__ __forceinline__ void cp_wait2() {
    asm volatile("cp.async.wait_group 2;");
}
__device__ __forceinline__ void ldsm4(uint32_t* r, uint32_t addr) {
    asm volatile("ldmatrix.sync.aligned.m8n8.x4.shared.b16 {%0,%1,%2,%3}, [%4];"
        : "=r"(r[0]), "=r"(r[1]), "=r"(r[2]), "=r"(r[3]) : "r"(addr));
}
__device__ __forceinline__ void mma16816(float* c, const uint32_t* a, const uint32_t* b) {
    asm volatile("mma.sync.aligned.m16n8k16.row.col.f32.f16.f16.f32 "
        "{%0,%1,%2,%3}, {%4,%5,%6,%7}, {%8,%9}, {%0,%1,%2,%3};"
        : "+f"(c[0]), "+f"(c[1]), "+f"(c[2]), "+f"(c[3])
        : "r"(a[0]), "r"(a[1]), "r"(a[2]), "r"(a[3]), "r"(b[0]), "r"(b[1]));
}

// ---------------- HMMA GEMM: plain fp16, fp32 accum --------------------------
// D = A @ B^T   (A [M][K] fp16, B [N][K] fp16)
// CTA tile 128x128, BK=32, 16 chunks, 3-stage cp.async.  (R11-proven config)
// epi: 2 = +res(f32) -> h16 ; 3 = gelu(acc+bias) -> h16 ; 4 = acc+bias+res(h16) -> f32
//      5 = merged QKV -> h16: w=bx>>2; Q,K get elu+1, V plain
#define HBM 128
#define HBN 128
#define HBK 32
#define LDP 40                      // padded row length in halves (80B)
#define SUBT (HBM*LDP*2)            // one 128x32 subtile = 10240 B
#define STAGE_B (2*SUBT)            // A + B = 20480 B
#define NCHUNK 16

__device__ __forceinline__ void load_chunk_dev(
    int c, int s, uint32_t sbase, int row0, int n0, int ldrow, int q0,
    const h16* A, const h16* B)
{
    const int k0 = c << 5;
    const uint32_t sA = sbase + s * STAGE_B;
    const uint32_t sB = sA + SUBT;
    const size_t ga = (size_t)(row0 + ldrow) * CDIM + k0;
    const size_t gb = (size_t)(n0 + ldrow) * CDIM + k0;
    cp16(sA + (ldrow * LDP + q0 * 8) * 2,       A + ga + q0 * 8);
    cp16(sA + (ldrow * LDP + (q0 + 1) * 8) * 2, A + ga + (q0 + 1) * 8);
    cp16(sB + (ldrow * LDP + q0 * 8) * 2,       B + gb + q0 * 8);
    cp16(sB + (ldrow * LDP + (q0 + 1) * 8) * 2, B + gb + (q0 + 1) * 8);
    cp_commit();
}

__global__ __launch_bounds__(256, 2) void gemm_hmma(
          const h16* __restrict__ A, const h16* __restrict__ Bbase,
          float* __restrict__ out,
          h16* __restrict__ out_h,
          const float* __restrict__ bias, const float* __restrict__ res,
          const h16* __restrict__ resh,
          int epi,
          h16* __restrict__ outK, h16* __restrict__ outV)
{
    extern __shared__ char smem[];
    const uint32_t sbase = smem_u32(smem);
    const int tid = threadIdx.x;
    const int wid = tid >> 5, lane = tid & 31;
    const int warp_m = wid >> 2;
    const int warp_n = wid & 3;
    const int row0 = blockIdx.y * HBM;

    int n0, e;                 // e: 0=elu+1->h16, 1=plain->h16, 2=+res->h16, 3=gelu->h16, 4=+bias+res->f32
    const h16* B;
    h16* oh;
    if (epi == 5) {
        const int w = blockIdx.x >> 2;
        n0 = (blockIdx.x & 3) * HBN;
        B = Bbase + (size_t)w * CDIM * CDIM;
        oh = (w == 0) ? out_h : ((w == 1) ? outK : outV);
        e = (w == 2) ? 1 : 0;
    } else {
        n0 = blockIdx.x * HBN;
        B = Bbase;
        oh = out_h;
        e = epi;
    }

    const int ldrow = tid >> 1;
    const int q0 = (tid & 1) * 2;

    float acc[4][4][4];
    #pragma unroll
    for (int i = 0; i < 4; i++)
        #pragma unroll
        for (int j = 0; j < 4; j++)
            #pragma unroll
            for (int ee = 0; ee < 4; ee++) acc[i][j][ee] = 0.0f;

    load_chunk_dev(0, 0, sbase, row0, n0, ldrow, q0, A, B);
    load_chunk_dev(1, 1, sbase, row0, n0, ldrow, q0, A, B);
    load_chunk_dev(2, 2, sbase, row0, n0, ldrow, q0, A, B);

    const int b_row_lo = (lane >> 4) & 1;
    const int b_kh     = (lane >> 3) & 1;
    const int b_r7     = lane & 7;

    for (int c = 0; c < NCHUNK; c++) {
        const int s = c % 3;
        cp_wait2();
        __syncthreads();

        const uint32_t sA = sbase + s * STAGE_B;
        const uint32_t sB = sA + SUBT;
        #pragma unroll
        for (int kk = 0; kk < HBK; kk += 16) {
            uint32_t b[4][2];
            #pragma unroll
            for (int fnp = 0; fnp < 2; fnp++) {
                uint32_t r4[4];
                const int r = warp_n * 32 + (2 * fnp + b_row_lo) * 8 + b_r7;
                ldsm4(r4, sB + (r * LDP + kk + 8 * b_kh) * 2);
                b[2 * fnp + 0][0] = r4[0]; b[2 * fnp + 0][1] = r4[1];
                b[2 * fnp + 1][0] = r4[2]; b[2 * fnp + 1][1] = r4[3];
            }
            uint32_t a[4][4];
            #pragma unroll
            for (int fm = 0; fm < 4; fm++) {
                const int r = warp_m * 64 + fm * 16 + (lane & 15);
                ldsm4(a[fm], sA + (r * LDP + kk + 8 * (lane >> 4)) * 2);
            }
            #pragma unroll
            for (int fm = 0; fm < 4; fm++)
                #pragma unroll
                for (int fn = 0; fn < 4; fn++)
                    mma16816(acc[fm][fn], a[fm], b[fn]);
        }
        __syncthreads();
        if (c + 3 < NCHUNK)
            load_chunk_dev(c + 3, s, sbase, row0, n0, ldrow, q0, A, B);
    }

    // ---------------- epilogue ----------------
    const int g = lane >> 2;
    const int t2 = (lane & 3) * 2;
    #pragma unroll
    for (int fm = 0; fm < 4; fm++) {
        #pragma unroll
        for (int fn = 0; fn < 4; fn++) {
            const int ra = row0 + warp_m * 64 + fm * 16 + g;
            const int rb = ra + 8;
            const int col = n0 + warp_n * 32 + fn * 8 + t2;
            float v0 = acc[fm][fn][0], v1 = acc[fm][fn][1];
            float v2 = acc[fm][fn][2], v3 = acc[fm][fn][3];
            const size_t ia = (size_t)ra * CDIM + col;
            const size_t ib = (size_t)rb * CDIM + col;

            if (e == 4) {
                const float b0 = bias[col], b1 = bias[col + 1];
                v0 += b0 + h2f(resh[ia]); v1 += b1 + h2f(resh[ia + 1]);
                v2 += b0 + h2f(resh[ib]); v3 += b1 + h2f(resh[ib + 1]);
                float2 pa; pa.x = v0; pa.y = v1;
                float2 pb; pb.x = v2; pb.y = v3;
                *(float2*)(out + ia) = pa;
                *(float2*)(out + ib) = pb;
            } else {
                if (e == 0) {
                    v0 = (v0 > 0.0f) ? (v0 + 1.0f) : expf(v0);
                    v1 = (v1 > 0.0f) ? (v1 + 1.0f) : expf(v1);
                    v2 = (v2 > 0.0f) ? (v2 + 1.0f) : expf(v2);
                    v3 = (v3 > 0.0f) ? (v3 + 1.0f) : expf(v3);
                } else if (e == 2) {
                    v0 += res[ia]; v1 += res[ia + 1];
                    v2 += res[ib]; v3 += res[ib + 1];
                } else if (e == 3) {
                    const float b0 = bias[col], b1 = bias[col + 1];
                    v0 += b0; v1 += b1; v2 += b0; v3 += b1;
                    v0 = 0.5f * v0 * (1.0f + erff(v0 * 0.70710678f));
                    v1 = 0.5f * v1 * (1.0f + erff(v1 * 0.70710678f));
                    v2 = 0.5f * v2 * (1.0f + erff(v2 * 0.70710678f));
                    v3 = 0.5f * v3 * (1.0f + erff(v3 * 0.70710678f));
                }
                h16 h0 = f2h(v0), h1 = f2h(v1), h2 = f2h(v2), h3 = f2h(v3);
                *(uint32_t*)(oh + ia) = (uint32_t)h0 | ((uint32_t)h1 << 16);
                *(uint32_t*)(oh + ib) = (uint32_t)h2 | ((uint32_t)h3 << 16);
            }
        }
    }
}

// ---------------- weight transpose -> fp16 (all 6 in one launch) --------------
__global__ void transpose6(const float* __restrict__ W0, const float* __restrict__ W1,
                           const float* __restrict__ W2, const float* __restrict__ W3,
                           const float* __restrict__ W4, const float* __restrict__ W5,
                           h16* __restrict__ Tbase) {
    __shared__ float t[32][33];
    const int z = blockIdx.z;
    const float* W = (z == 0) ? W0 : (z == 1) ? W1 : (z == 2) ? W2 : (z == 3) ? W3 : (z == 4) ? W4 : W5;
    h16* T = Tbase + (size_t)z * CDIM * CDIM;
    const int n = blockIdx.x * 32 + threadIdx.x;
    #pragma unroll
    for (int r = 0; r < 4; ++r) {
        const int k = blockIdx.y * 32 + threadIdx.y + r * 8;
        t[threadIdx.y + r * 8][threadIdx.x] = W[(size_t)k * CDIM + n];
    }
    __syncthreads();
    #pragma unroll
    for (int r = 0; r < 4; ++r) {
        const int n_out = blockIdx.x * 32 + threadIdx.y + r * 8;
        const int k_out = blockIdx.y * 32 + threadIdx.x;
        T[(size_t)n_out * CDIM + k_out] = f2h(t[threadIdx.x][threadIdx.y + r * 8]);
    }
}

// ---------------- LayerNorm: warp-per-row, no block barriers ------------------
__global__ void ln_f32(const float* __restrict__ x,
                       const float* __restrict__ gam,
                       const float* __restrict__ bet,
                       h16* __restrict__ oh) {
    const int warp = threadIdx.x >> 5, lane = threadIdx.x & 31;
    const int row = blockIdx.x * 8 + warp;
    const float4* xr = (const float4*)(x + (size_t)row * CDIM);
    float4 v[4];
    float s = 0.0f, sq = 0.0f;
    #pragma unroll
    for (int j = 0; j < 4; j++) {
        v[j] = xr[j * 32 + lane];
        s  += v[j].x + v[j].y + v[j].z + v[j].w;
        sq += v[j].x * v[j].x + v[j].y * v[j].y + v[j].z * v[j].z + v[j].w * v[j].w;
    }
    #pragma unroll
    for (int o = 16; o; o >>= 1) {
        s  += __shfl_xor_sync(0xffffffffu, s,  o);
        sq += __shfl_xor_sync(0xffffffffu, sq, o);
    }
    const float mu = s * (1.0f / CDIM);
    const float rstd = rsqrtf(sq * (1.0f / CDIM) - mu * mu + EPS_LN);
    uint32_t* orow = (uint32_t*)(oh + (size_t)row * CDIM);
    const float4* gr = (const float4*)gam;
    const float4* br = (const float4*)bet;
    #pragma unroll
    for (int j = 0; j < 4; j++) {
        const float4 g4 = gr[j * 32 + lane];
        const float4 b4 = br[j * 32 + lane];
        const float o0 = (v[j].x - mu) * rstd * g4.x + b4.x;
        const float o1 = (v[j].y - mu) * rstd * g4.y + b4.y;
        const float o2 = (v[j].z - mu) * rstd * g4.z + b4.z;
        const float o3 = (v[j].w - mu) * rstd * g4.w + b4.w;
        orow[(j * 32 + lane) * 2 + 0] = (uint32_t)f2h(o0) | ((uint32_t)f2h(o1) << 16);
        orow[(j * 32 + lane) * 2 + 1] = (uint32_t)f2h(o2) | ((uint32_t)f2h(o3) << 16);
    }
}

__global__ void ln_f16(const h16* __restrict__ xh,
                       const float* __restrict__ gam,
                       const float* __restrict__ bet,
                       h16* __restrict__ oh) {
    const int warp = threadIdx.x >> 5, lane = threadIdx.x & 31;
    const int row = blockIdx.x * 8 + warp;
    const uint2* xr = (const uint2*)(xh + (size_t)row * CDIM);
    float vx[4][4];
    float s = 0.0f, sq = 0.0f;
    #pragma unroll
    for (int j = 0; j < 4; j++) {
        const uint2 u = xr[j * 32 + lane];
        vx[j][0] = h2f((h16)(u.x & 0xffff));
        vx[j][1] = h2f((h16)(u.x >> 16));
        vx[j][2] = h2f((h16)(u.y & 0xffff));
        vx[j][3] = h2f((h16)(u.y >> 16));
        #pragma unroll
        for (int e = 0; e < 4; e++) { s += vx[j][e]; sq += vx[j][e] * vx[j][e]; }
    }
    #pragma unroll
    for (int o = 16; o; o >>= 1) {
        s  += __shfl_xor_sync(0xffffffffu, s,  o);
        sq += __shfl_xor_sync(0xffffffffu, sq, o);
    }
    const float mu = s * (1.0f / CDIM);
    const float rstd = rsqrtf(sq * (1.0f / CDIM) - mu * mu + EPS_LN);
    uint32_t* orow = (uint32_t*)(oh + (size_t)row * CDIM);
    const float4* gr = (const float4*)gam;
    const float4* br = (const float4*)bet;
    #pragma unroll
    for (int j = 0; j < 4; j++) {
        const float4 g4 = gr[j * 32 + lane];
        const float4 b4 = br[j * 32 + lane];
        const float o0 = (vx[j][0] - mu) * rstd * g4.x + b4.x;
        const float o1 = (vx[j][1] - mu) * rstd * g4.y + b4.y;
        const float o2 = (vx[j][2] - mu) * rstd * g4.z + b4.z;
        const float o3 = (vx[j][3] - mu) * rstd * g4.w + b4.w;
        orow[(j * 32 + lane) * 2 + 0] = (uint32_t)f2h(o0) | ((uint32_t)f2h(o1) << 16);
        orow[(j * 32 + lane) * 2 + 1] = (uint32_t)f2h(o2) | ((uint32_t)f2h(o3) << 16);
    }
}

// ---------------- zero KV/Ksum ----------------
__global__ void zero_kv_kernel() {
    int i = blockIdx.x * blockDim.x + threadIdx.x;
    if (i < BATCH * NHEAD * HDIM * HDIM) g_KV[i] = 0.0f;
    if (i < BATCH * NHEAD * HDIM)        g_Ksum[i] = 0.0f;
}

// ---------------- KV = sum_s K[s] (outer) v[s]; Ksum = sum_s K[s] -------------
// 16-row staging, uint32 global loads, register prefetch, float4 smem V reads.
__global__ void kv_kernel() {
    const int bh = blockIdx.x;
    const int b = bh >> 4, h = bh & 15;
    const int tid = threadIdx.x;
    const int d = tid >> 3;
    const int vb = (tid & 7) << 2;
    __shared__ float sK[16][32];
    __shared__ float sV[16][32];

    const int lrow  = tid >> 4;      // 0..15
    const int lpair = tid & 15;      // 0..15 (h16 pair)

    float a0 = 0, a1 = 0, a2 = 0, a3 = 0, ks = 0;
    const h16* Kbase = g_Kh + (size_t)b * SEQ * CDIM + h * HDIM;
    const h16* Vbase = g_Vh + (size_t)b * SEQ * CDIM + h * HDIM;
    const int s0 = blockIdx.y * (SEQ / 8);   // 512 tokens/block

    size_t so = (size_t)(s0 + lrow) * CDIM + lpair * 2;
    uint32_t kn = *(const uint32_t*)(Kbase + so);
    uint32_t vn = *(const uint32_t*)(Vbase + so);

    for (int ssi = 0; ssi < SEQ / 8; ssi += 16) {
        const uint32_t kc = kn, vc = vn;
        if (ssi + 16 < SEQ / 8) {
            const size_t s2 = (size_t)(s0 + ssi + 16 + lrow) * CDIM + lpair * 2;
            kn = *(const uint32_t*)(Kbase + s2);
            vn = *(const uint32_t*)(Vbase + s2);
        }
        sK[lrow][lpair * 2 + 0] = h2f((h16)(kc & 0xffff));
        sK[lrow][lpair * 2 + 1] = h2f((h16)(kc >> 16));
        sV[lrow][lpair * 2 + 0] = h2f((h16)(vc & 0xffff));
        sV[lrow][lpair * 2 + 1] = h2f((h16)(vc >> 16));
        __syncthreads();
        #pragma unroll
        for (int si = 0; si < 16; si++) {
            const float kd = sK[si][d];
            const float4 v4 = *(const float4*)&sV[si][vb];
            ks += kd;
            a0 = fmaf(kd, v4.x, a0);
            a1 = fmaf(kd, v4.y, a1);
            a2 = fmaf(kd, v4.z, a2);
            a3 = fmaf(kd, v4.w, a3);
        }
        __syncthreads();
    }
    float* kvp = g_KV + (size_t)bh * HDIM * HDIM + d * HDIM + vb;
    atomicAdd(kvp + 0, a0);
    atomicAdd(kvp + 1, a1);
    atomicAdd(kvp + 2, a2);
    atomicAdd(kvp + 3, a3);
    if ((tid & 7) == 0) atomicAdd(&g_Ksum[bh * HDIM + d], ks);
}

// ---------------- msg: per token-head 32x32 matvec -> fp16 --------------------
// Two tokens per pass share each sKV LDS.
__global__ void msg_kernel() {
    const int bh = blockIdx.x;
    const int b = bh >> 4, h = bh & 15;
    const int tid = threadIdx.x;
    const int warp = tid >> 5, lane = tid & 31;
    __shared__ float sKV[HDIM * HDIM];
    __shared__ float sKs[HDIM];

    for (int i = tid; i < HDIM * HDIM; i += 256) sKV[i] = g_KV[(size_t)bh * HDIM * HDIM + i];
    if (tid < HDIM) sKs[tid] = g_Ksum[bh * HDIM + tid];
    __syncthreads();

    const int tokBase = blockIdx.y * 64 + warp * 8;
    for (int tt = 0; tt < 8; tt += 2) {
        const int sA = tokBase + tt;
        const size_t offA = ((size_t)b * SEQ + sA) * CDIM + h * HDIM + lane;
        const size_t offB = offA + CDIM;
        const float qa = h2f(g_Qh[offA]);
        const float qb = h2f(g_Qh[offB]);
        float za = qa * sKs[lane];
        float zb = qb * sKs[lane];
        #pragma unroll
        for (int o = 16; o; o >>= 1) {
            za += __shfl_xor_sync(0xffffffffu, za, o);
            zb += __shfl_xor_sync(0xffffffffu, zb, o);
        }
        float fa = 0.0f, fb = 0.0f;
        #pragma unroll
        for (int dd = 0; dd < HDIM; dd++) {
            const float kvv = sKV[dd * HDIM + lane];
            fa = fmaf(__shfl_sync(0xffffffffu, qa, dd), kvv, fa);
            fb = fmaf(__shfl_sync(0xffffffffu, qb, dd), kvv, fb);
        }
        g_Mh[offA] = f2h(fa / (za + EPS_ATT));
        g_Mh[offB] = f2h(fb / (zb + EPS_ATT));
    }
}

// ---------------- host side ----------------
extern "C" void kernel_launch(void* const* d_in, const int* in_sizes, int n_in,
                              void* d_out, int out_size) {
    const float* x     = (const float*)d_in[0];
    const float* Wq    = (const float*)d_in[1];
    const float* Wk    = (const float*)d_in[2];
    const float* Wv    = (const float*)d_in[3];
    const float* Wm    = (const float*)d_in[4];
    const float* W1    = (const float*)d_in[5];
    const float* b1    = (const float*)d_in[6];
    const float* W2    = (const float*)d_in[7];
    const float* b2    = (const float*)d_in[8];
    const float* g_att = (const float*)d_in[9];
    const float* b_att = (const float*)d_in[10];
    const float* g_ffn = (const float*)d_in[11];
    const float* b_ffn = (const float*)d_in[12];
    float* out = (float*)d_out;

    h16 *p_Qh, *p_Kh, *p_Vh, *p_x2h, *p_Ah, *p_Mh, *p_Whi;
    cudaGetSymbolAddress((void**)&p_Qh,  g_Qh);
    cudaGetSymbolAddress((void**)&p_Kh,  g_Kh);
    cudaGetSymbolAddress((void**)&p_Vh,  g_Vh);
    cudaGetSymbolAddress((void**)&p_x2h, g_x2h);
    cudaGetSymbolAddress((void**)&p_Ah,  g_Ah);
    cudaGetSymbolAddress((void**)&p_Mh,  g_Mh);
    cudaGetSymbolAddress((void**)&p_Whi, g_Whi);

    const int SMEM = 3 * STAGE_B;   // 61440
    cudaFuncSetAttribute(gemm_hmma, cudaFuncAttributeMaxDynamicSharedMemorySize, SMEM);

    const size_t WS = (size_t)CDIM * CDIM;
    dim3 tgrid(16, 16, 6);
    dim3 tblk(32, 8);
    dim3 ggrid(CDIM / HBN, MROWS / HBM);        // (4, 256)
    dim3 qkvgrid(3 * CDIM / HBN, MROWS / HBM);  // (12, 256)

    zero_kv_kernel<<<(BATCH * NHEAD * HDIM * HDIM + 255) / 256, 256>>>();
    transpose6<<<tgrid, tblk>>>(Wq, Wk, Wv, Wm, W1, W2, p_Whi);
    // h = LN(x) -> Ah
    ln_f32<<<MROWS / 8, 256>>>(x, g_att, b_att, p_Ah);
    // merged QKV (Q = elu+1, K = elu+1, V = plain) -> fp16
    gemm_hmma<<<qkvgrid, 256, SMEM>>>(p_Ah, p_Whi, nullptr, p_Qh, nullptr, nullptr, nullptr, 5, p_Kh, p_Vh);
    // KV / Ksum
    kv_kernel<<<dim3(BATCH * NHEAD, 8), 256>>>();
    // msg -> Mh
    msg_kernel<<<dim3(BATCH * NHEAD, SEQ / 64), 256>>>();
    // x2 = x + msg @ Wm  -> fp16
    gemm_hmma<<<ggrid, 256, SMEM>>>(p_Mh, p_Whi + 3*WS, nullptr, p_x2h, nullptr, x, nullptr, 2, nullptr, nullptr);
    // h2 = LN(x2) -> Ah
    ln_f16<<<MROWS / 8, 256>>>(p_x2h, g_ffn, b_ffn, p_Ah);
    // f1 = gelu(h2 @ W1 + b1) -> Mh
    gemm_hmma<<<ggrid, 256, SMEM>>>(p_Ah, p_Whi + 4*WS, nullptr, p_Mh, b1, nullptr, nullptr, 3, nullptr, nullptr);
    // out = x2 + f1 @ W2 + b2  (x2 read as fp16)
    gemm_hmma<<<ggrid, 256, SMEM>>>(p_Mh, p_Whi + 5*WS, out, nullptr, b2, nullptr, p_x2h, 4, nullptr, nullptr);
}